// round 7
// baseline (speedup 1.0000x reference)
#include <cuda_runtime.h>
#include <cuda_bf16.h>
#include <cstdint>
#include <math.h>

// ---------------------------------------------------------------- constants
#define BB 4
#define NN 20000
#define SS 2048
#define CC 64
#define DD 64
#define INV_T 1.4285714285714286f
#define C2EXP 2.0609929155556624f   // INV_T * log2(e)

#define TILE_M 64
#define TN 128
#define NCH (SS / TN)          // 16 column chunks
#define TPB (SS / TILE_M)      // 32 row tiles per batch
#define NCTA (BB * TPB)        // 128 loss CTAs

// ---------------------------------------------------------------- scratch
__device__ __align__(256) __nv_bfloat16 g_Vn[(size_t)BB * SS * CC];
__device__ __align__(256) __nv_bfloat16 g_Fn[(size_t)BB * SS * CC];
__device__ int   g_inv_perm[BB * NN];
__device__ float g_partials[NCTA];
__device__ int   g_count;   // zero-init; reset by last CTA each run

// ---------------------------------------------------------------- helpers
__device__ __forceinline__ uint32_t smem_u32(const void* p) {
    uint32_t a;
    asm("{ .reg .u64 t; cvta.to.shared.u64 t, %1; cvt.u32.u64 %0, t; }" : "=r"(a) : "l"(p));
    return a;
}
__device__ __forceinline__ void cpa16(uint32_t dst, const void* src) {
    asm volatile("cp.async.cg.shared.global [%0], [%1], 16;" :: "r"(dst), "l"(src));
}
#define CP_COMMIT() asm volatile("cp.async.commit_group;" ::: "memory")
#define CP_WAIT(n)  asm volatile("cp.async.wait_group %0;" :: "n"(n) : "memory")

#define LDSM4(r0, r1, r2, r3, addr)                                            \
    asm volatile("ldmatrix.sync.aligned.m8n8.x4.shared.b16 {%0,%1,%2,%3}, [%4];" \
                 : "=r"(r0), "=r"(r1), "=r"(r2), "=r"(r3) : "r"(addr))

__device__ __forceinline__ void mma16816(float* c, const uint32_t* a,
                                         uint32_t b0, uint32_t b1) {
    asm volatile(
        "mma.sync.aligned.m16n8k16.row.col.f32.bf16.bf16.f32 "
        "{%0,%1,%2,%3}, {%4,%5,%6,%7}, {%8,%9}, {%0,%1,%2,%3};"
        : "+f"(c[0]), "+f"(c[1]), "+f"(c[2]), "+f"(c[3])
        : "r"(a[0]), "r"(a[1]), "r"(a[2]), "r"(a[3]), "r"(b0), "r"(b1));
}
__device__ __forceinline__ float ex2f(float x) {
    float r; asm("ex2.approx.f32 %0, %1;" : "=f"(r) : "f"(x)); return r;
}

// ---------------------------------------------------------------- kernel 0
// Fused: scatter inverse permutation + vehicle gather/normalize.
// Grid: 256 CTAs x 256 threads.  CTAs 0-127: 8 warps x 8 rows gather (MLP=8).
// All CTAs participate in the scatter.
__global__ __launch_bounds__(256) void k0(
    const float* __restrict__ dv, const int* __restrict__ vcoor,
    const int* __restrict__ shuf, const int* __restrict__ samp_idx)
{
    const int tid = threadIdx.x;
    const int w   = tid >> 5;
    const int l   = tid & 31;
    const int cta = blockIdx.x;

    // scatter: inv[shuf[i]] = i   (striped over all 65536 threads)
    for (int i = cta * 256 + tid; i < BB * NN; i += 256 * 256) {
        int b = i / NN;
        int local = i - b * NN;
        g_inv_perm[b * NN + shuf[i]] = local;
    }

    if (cta >= 128) return;

    // vehicle gather: warp gw handles rows gw*8 .. gw*8+7 (MLP-batched)
    int rbase = (cta * 8 + w) * 8;
    const float* src[8];
    #pragma unroll
    for (int k = 0; k < 8; k++) {
        int r = rbase + k, b = r >> 11, s = r & 2047;
        int samp = __ldg(&samp_idx[b * SS + s]);
        const int* cp = vcoor + ((size_t)b * NN + samp) * 3;
        int c0 = cp[0] >> 3, c1 = cp[1] >> 3, c2 = cp[2] >> 3;
        src[k] = dv + ((((size_t)b * DD + c0) * DD + c1) * DD + c2) * (size_t)CC;
    }
    float v0[8], v1[8];
    #pragma unroll
    for (int k = 0; k < 8; k++) { v0[k] = src[k][l]; v1[k] = src[k][l + 32]; }
    #pragma unroll
    for (int k = 0; k < 8; k++) {
        float ssq = v0[k] * v0[k] + v1[k] * v1[k];
        #pragma unroll
        for (int o = 16; o; o >>= 1) ssq += __shfl_xor_sync(0xffffffffu, ssq, o);
        float inv = 1.0f / fmaxf(sqrtf(ssq), 1e-12f);
        size_t rb = (size_t)(rbase + k) * CC;
        g_Vn[rb + l]      = __float2bfloat16(v0[k] * inv);
        g_Vn[rb + l + 32] = __float2bfloat16(v1[k] * inv);
    }
}

// ---------------------------------------------------------------- kernel 1
// fusion gather (through inverse permutation), MLP-batched, 128 CTAs.
__global__ __launch_bounds__(256) void k1(
    const float* __restrict__ df, const int* __restrict__ fcoor,
    const int* __restrict__ samp_idx)
{
    const int tid = threadIdx.x;
    const int w   = tid >> 5;
    const int l   = tid & 31;

    int rbase = (blockIdx.x * 8 + w) * 8;
    const float* src[8];
    #pragma unroll
    for (int k = 0; k < 8; k++) {
        int r = rbase + k, b = r >> 11, s = r & 2047;
        int samp = __ldg(&samp_idx[b * SS + s]);
        int fid  = g_inv_perm[b * NN + samp];
        const int* cp = fcoor + ((size_t)b * NN + fid) * 3;
        int c0 = cp[0] >> 3, c1 = cp[1] >> 3, c2 = cp[2] >> 3;
        src[k] = df + ((((size_t)b * DD + c0) * DD + c1) * DD + c2) * (size_t)CC;
    }
    float v0[8], v1[8];
    #pragma unroll
    for (int k = 0; k < 8; k++) { v0[k] = src[k][l]; v1[k] = src[k][l + 32]; }
    #pragma unroll
    for (int k = 0; k < 8; k++) {
        float ssq = v0[k] * v0[k] + v1[k] * v1[k];
        #pragma unroll
        for (int o = 16; o; o >>= 1) ssq += __shfl_xor_sync(0xffffffffu, ssq, o);
        float inv = 1.0f / fmaxf(sqrtf(ssq), 1e-12f);
        size_t rb = (size_t)(rbase + k) * CC;
        g_Fn[rb + l]      = __float2bfloat16(v0[k] * inv);
        g_Fn[rb + l + 32] = __float2bfloat16(v1[k] * inv);
    }
}

// ---------------------------------------------------------------- kernel 2
// Fused bf16 mma.sync GEMM (64 x 2048 x 64 per CTA) + exp/rowsum/diag + loss.
__global__ __launch_bounds__(256, 1) void k_loss(float* __restrict__ out) {
    __shared__ __align__(128) unsigned char sA[TILE_M * 128];      // 8 KB
    __shared__ __align__(128) unsigned char sB[2][TN * 128];       // 32 KB
    __shared__ float ssum[2][TILE_M];
    __shared__ float sdiag[TILE_M];
    __shared__ float sloss[TILE_M];

    const int tid = threadIdx.x;
    const int w   = tid >> 5;
    const int l   = tid & 31;
    const int cta = blockIdx.x;
    const int b      = cta >> 5;
    const int mytile = cta & 31;
    const int g  = w >> 2;          // column half group
    const int wr = (w & 3) * 16;    // warp row base (local)

    const __nv_bfloat16* Ag = g_Vn + ((size_t)b * SS + (size_t)mytile * TILE_M) * CC;
    const __nv_bfloat16* Fg = g_Fn + (size_t)b * SS * CC;

    const uint32_t sAu  = smem_u32(sA);
    const uint32_t sBu0 = smem_u32(sB[0]);
    const uint32_t sBu1 = smem_u32(sB[1]);

    // prologue: A + B0 (group), B1 (group)
    for (int i = tid; i < 512; i += 256) {
        int r = i >> 3, c = i & 7;
        cpa16(sAu + r * 128 + ((c ^ (r & 7)) << 4), (const char*)Ag + r * 128 + c * 16);
    }
    for (int i = tid; i < 1024; i += 256) {
        int r = i >> 3, c = i & 7;
        cpa16(sBu0 + r * 128 + ((c ^ (r & 7)) << 4), (const char*)Fg + r * 128 + c * 16);
    }
    CP_COMMIT();
    for (int i = tid; i < 1024; i += 256) {
        int r = i >> 3, c = i & 7;
        cpa16(sBu1 + r * 128 + ((c ^ (r & 7)) << 4),
              (const char*)Fg + (size_t)TN * 128 + r * 128 + c * 16);
    }
    CP_COMMIT();
    CP_WAIT(1);
    __syncthreads();

    // A fragments (constant across all chunks)
    uint32_t afr[4][4];
    {
        int row = wr + (l & 15);
        #pragma unroll
        for (int kk = 0; kk < 4; kk++) {
            int kb = kk * 32 + (l >> 4) * 16;
            uint32_t ad = sAu + row * 128 + (((kb >> 4) ^ (row & 7)) << 4);
            LDSM4(afr[kk][0], afr[kk][1], afr[kk][2], afr[kk][3], ad);
        }
    }

    const int r0 = wr + (l >> 2), r1 = r0 + 8;
    const bool mygrp = (g == (mytile & 1));
    const int dct = mytile >> 1;
    float rs0 = 0.f, rs1 = 0.f, d0 = 0.f, d1 = 0.f;

    const int nlane  = (l & 7) + ((l >> 4) << 3);
    const int kblane = ((l >> 3) & 1) * 16;

    for (int ct = 0; ct < NCH; ++ct) {
        const uint32_t sBu = (ct & 1) ? sBu1 : sBu0;
        const bool dg = mygrp && (ct == dct);

        #pragma unroll
        for (int jp = 0; jp < 4; ++jp) {
            float a0[4] = {0.f, 0.f, 0.f, 0.f};
            float a1[4] = {0.f, 0.f, 0.f, 0.f};
            #pragma unroll
            for (int kk = 0; kk < 4; ++kk) {
                int n  = g * 64 + jp * 16 + nlane;
                int kb = kk * 32 + kblane;
                uint32_t ad = sBu + n * 128 + (((kb >> 4) ^ (n & 7)) << 4);
                uint32_t b0, b1, b2, b3;
                LDSM4(b0, b1, b2, b3, ad);
                mma16816(a0, afr[kk], b0, b1);
                mma16816(a1, afr[kk], b2, b3);
            }
            int c00 = jp * 16 + (l & 3) * 2;
            int c10 = c00 + 8;
            if (dg) {
                if (c00     == r0) d0 = a0[0];
                if (c00 + 1 == r0) d0 = a0[1];
                if (c10     == r0) d0 = a1[0];
                if (c10 + 1 == r0) d0 = a1[1];
                if (c00     == r1) d1 = a0[2];
                if (c00 + 1 == r1) d1 = a0[3];
                if (c10     == r1) d1 = a1[2];
                if (c10 + 1 == r1) d1 = a1[3];
            }
            rs0 += ex2f(a0[0] * C2EXP) + ex2f(a0[1] * C2EXP)
                 + ex2f(a1[0] * C2EXP) + ex2f(a1[1] * C2EXP);
            rs1 += ex2f(a0[2] * C2EXP) + ex2f(a0[3] * C2EXP)
                 + ex2f(a1[2] * C2EXP) + ex2f(a1[3] * C2EXP);
        }

        __syncthreads();
        if (ct + 2 < NCH) {
            uint32_t dstB = (ct & 1) ? sBu1 : sBu0;
            const char* src = (const char*)Fg + (size_t)(ct + 2) * TN * 128;
            for (int i = tid; i < 1024; i += 256) {
                int r = i >> 3, c = i & 7;
                cpa16(dstB + r * 128 + ((c ^ (r & 7)) << 4), src + r * 128 + c * 16);
            }
            CP_COMMIT();
            CP_WAIT(1);
            __syncthreads();
        } else if (ct + 1 < NCH) {
            CP_WAIT(0);
            __syncthreads();
        }
    }

    // reduce within quads
    #pragma unroll
    for (int o = 1; o <= 2; o <<= 1) {
        rs0 += __shfl_xor_sync(0xffffffffu, rs0, o);
        rs1 += __shfl_xor_sync(0xffffffffu, rs1, o);
        d0  += __shfl_xor_sync(0xffffffffu, d0, o);
        d1  += __shfl_xor_sync(0xffffffffu, d1, o);
    }
    if ((l & 3) == 0) {
        ssum[g][r0] = rs0;
        ssum[g][r1] = rs1;
        if (mygrp) { sdiag[r0] = d0; sdiag[r1] = d1; }
    }
    __syncthreads();

    if (tid < TILE_M) {
        float tot = ssum[0][tid] + ssum[1][tid];
        sloss[tid] = logf(tot) - sdiag[tid] * INV_T;
    }
    __syncthreads();

    if (tid == 0) {
        float part = 0.f;
        #pragma unroll
        for (int i = 0; i < TILE_M; ++i) part += sloss[i];
        g_partials[cta] = part * (1.0f / (float)SS);
        __threadfence();
        int n = atomicAdd(&g_count, 1);
        if (n == NCTA - 1) {
            __threadfence();
            const volatile float* gp = (const volatile float*)g_partials;
            float tot = 0.f;
            for (int i = 0; i < NCTA; ++i) tot += gp[i];
            out[0] = tot;
            g_count = 0;   // reset for next graph replay
        }
    }
}

// ---------------------------------------------------------------- launch
extern "C" void kernel_launch(void* const* d_in, const int* in_sizes, int n_in,
                              void* d_out, int out_size) {
    const float* dv    = (const float*)d_in[0];
    const int*   vcoor = (const int*)  d_in[1];
    const float* df    = (const float*)d_in[2];
    const int*   fcoor = (const int*)  d_in[3];
    const int*   shuf  = (const int*)  d_in[4];
    // d_in[5] = vehicle_points (unused)
    const int*   samp  = (const int*)  d_in[6];

    k0<<<256, 256>>>(dv, vcoor, shuf, samp);
    k1<<<128, 256>>>(df, fcoor, samp);
    k_loss<<<NCTA, 256>>>((float*)d_out);
}

// round 8
// speedup vs baseline: 1.1157x; 1.1157x over previous
#include <cuda_runtime.h>
#include <cuda_bf16.h>
#include <cstdint>
#include <math.h>

// ---------------------------------------------------------------- constants
#define BB 4
#define NN 20000
#define SS 2048
#define CC 64
#define DD 64
#define INV_T 1.4285714285714286f
#define C2EXP 2.0609929155556624f   // INV_T * log2(e)

#define TILE_M 64
#define TN 128
#define NCH (SS / TN)          // 16 column chunks
#define TPB (SS / TILE_M)      // 32 row tiles per batch
#define NCTA (BB * TPB)        // 128 loss CTAs

// ---------------------------------------------------------------- scratch
__device__ __align__(256) __nv_bfloat16 g_Vn[(size_t)BB * SS * CC];
__device__ __align__(256) __nv_bfloat16 g_Fn[(size_t)BB * SS * CC];
__device__ int   g_inv_perm[BB * NN];
__device__ float g_partials[NCTA];
__device__ int   g_count;   // zero-init; reset by last CTA each run

// ---------------------------------------------------------------- helpers
__device__ __forceinline__ uint32_t smem_u32(const void* p) {
    uint32_t a;
    asm("{ .reg .u64 t; cvta.to.shared.u64 t, %1; cvt.u32.u64 %0, t; }" : "=r"(a) : "l"(p));
    return a;
}
__device__ __forceinline__ void cpa16(uint32_t dst, const void* src) {
    asm volatile("cp.async.cg.shared.global [%0], [%1], 16;" :: "r"(dst), "l"(src));
}
#define CP_COMMIT() asm volatile("cp.async.commit_group;" ::: "memory")
#define CP_WAIT(n)  asm volatile("cp.async.wait_group %0;" :: "n"(n) : "memory")

#define LDSM4(r0, r1, r2, r3, addr)                                            \
    asm volatile("ldmatrix.sync.aligned.m8n8.x4.shared.b16 {%0,%1,%2,%3}, [%4];" \
                 : "=r"(r0), "=r"(r1), "=r"(r2), "=r"(r3) : "r"(addr))

__device__ __forceinline__ void mma16816(float* c, const uint32_t* a,
                                         uint32_t b0, uint32_t b1) {
    asm volatile(
        "mma.sync.aligned.m16n8k16.row.col.f32.bf16.bf16.f32 "
        "{%0,%1,%2,%3}, {%4,%5,%6,%7}, {%8,%9}, {%0,%1,%2,%3};"
        : "+f"(c[0]), "+f"(c[1]), "+f"(c[2]), "+f"(c[3])
        : "r"(a[0]), "r"(a[1]), "r"(a[2]), "r"(a[3]), "r"(b0), "r"(b1));
}
__device__ __forceinline__ float ex2f(float x) {
    float r; asm("ex2.approx.f32 %0, %1;" : "=f"(r) : "f"(x)); return r;
}
__device__ __forceinline__ void stcg_bf2(__nv_bfloat16* p, __nv_bfloat162 v) {
    asm volatile("st.global.cg.b32 [%0], %1;" :: "l"(p), "r"(*(uint32_t*)&v));
}

// ---------------------------------------------------------------- kernel 0
// Spatially split: CTAs 0-255 gather+normalize V (4 rows/warp);
//                  CTAs 256-383 scatter the inverse permutation.
__global__ __launch_bounds__(256) void k0(
    const float* __restrict__ dv, const int* __restrict__ vcoor,
    const int* __restrict__ shuf, const int* __restrict__ samp_idx)
{
    const int tid = threadIdx.x;
    const int w   = tid >> 5;
    const int l   = tid & 31;
    const int cta = blockIdx.x;

    if (cta >= 256) {
        // scatter: inv[shuf[i]] = i  over 128 CTAs
        for (int i = (cta - 256) * 256 + tid; i < BB * NN; i += 128 * 256) {
            int b = i / NN;
            int local = i - b * NN;
            g_inv_perm[b * NN + shuf[i]] = local;
        }
        return;
    }

    // vehicle gather: warp handles 4 rows (MLP-batched)
    int rbase = (cta * 8 + w) * 4;
    const float* src[4];
    #pragma unroll
    for (int k = 0; k < 4; k++) {
        int r = rbase + k, b = r >> 11, s = r & 2047;
        int samp = __ldg(&samp_idx[b * SS + s]);
        const int* cp = vcoor + ((size_t)b * NN + samp) * 3;
        int c0 = cp[0] >> 3, c1 = cp[1] >> 3, c2 = cp[2] >> 3;
        src[k] = dv + ((((size_t)b * DD + c0) * DD + c1) * DD + c2) * (size_t)CC;
    }
    float v0[4], v1[4];
    #pragma unroll
    for (int k = 0; k < 4; k++) { v0[k] = src[k][l]; v1[k] = src[k][l + 32]; }
    #pragma unroll
    for (int k = 0; k < 4; k++) {
        float ssq = v0[k] * v0[k] + v1[k] * v1[k];
        #pragma unroll
        for (int o = 16; o; o >>= 1) ssq += __shfl_xor_sync(0xffffffffu, ssq, o);
        float inv = 1.0f / fmaxf(sqrtf(ssq), 1e-12f);
        size_t rb = (size_t)(rbase + k) * CC;
        // lane pairs: lane writes elements (2l, 2l+1)? keep simple: two scalar stores
        g_Vn[rb + l]      = __float2bfloat16(v0[k] * inv);
        g_Vn[rb + l + 32] = __float2bfloat16(v1[k] * inv);
    }
}

// ---------------------------------------------------------------- kernel 1
// fusion gather (through inverse permutation), 256 CTAs x 4 rows/warp.
__global__ __launch_bounds__(256) void k1(
    const float* __restrict__ df, const int* __restrict__ fcoor,
    const int* __restrict__ samp_idx)
{
    const int tid = threadIdx.x;
    const int w   = tid >> 5;
    const int l   = tid & 31;

    int rbase = (blockIdx.x * 8 + w) * 4;
    const float* src[4];
    #pragma unroll
    for (int k = 0; k < 4; k++) {
        int r = rbase + k, b = r >> 11, s = r & 2047;
        int samp = __ldg(&samp_idx[b * SS + s]);
        int fid  = g_inv_perm[b * NN + samp];
        const int* cp = fcoor + ((size_t)b * NN + fid) * 3;
        int c0 = cp[0] >> 3, c1 = cp[1] >> 3, c2 = cp[2] >> 3;
        src[k] = df + ((((size_t)b * DD + c0) * DD + c1) * DD + c2) * (size_t)CC;
    }
    float v0[4], v1[4];
    #pragma unroll
    for (int k = 0; k < 4; k++) { v0[k] = src[k][l]; v1[k] = src[k][l + 32]; }
    #pragma unroll
    for (int k = 0; k < 4; k++) {
        float ssq = v0[k] * v0[k] + v1[k] * v1[k];
        #pragma unroll
        for (int o = 16; o; o >>= 1) ssq += __shfl_xor_sync(0xffffffffu, ssq, o);
        float inv = 1.0f / fmaxf(sqrtf(ssq), 1e-12f);
        size_t rb = (size_t)(rbase + k) * CC;
        g_Fn[rb + l]      = __float2bfloat16(v0[k] * inv);
        g_Fn[rb + l + 32] = __float2bfloat16(v1[k] * inv);
    }
}

// ---------------------------------------------------------------- kernel 2
// Fused bf16 mma.sync GEMM (64 x 2048 x 64 per CTA) + exp/rowsum/diag + loss.
__global__ __launch_bounds__(256, 1) void k_loss(float* __restrict__ out) {
    __shared__ __align__(128) unsigned char sA[TILE_M * 128];      // 8 KB
    __shared__ __align__(128) unsigned char sB[2][TN * 128];       // 32 KB
    __shared__ float ssum[2][TILE_M];
    __shared__ float sdiag[TILE_M];
    __shared__ float sloss[TILE_M];

    const int tid = threadIdx.x;
    const int w   = tid >> 5;
    const int l   = tid & 31;
    const int cta = blockIdx.x;
    const int b      = cta >> 5;
    const int mytile = cta & 31;
    const int g  = w >> 2;          // column half group
    const int wr = (w & 3) * 16;    // warp row base (local)

    const __nv_bfloat16* Ag = g_Vn + ((size_t)b * SS + (size_t)mytile * TILE_M) * CC;
    const __nv_bfloat16* Fg = g_Fn + (size_t)b * SS * CC;

    const uint32_t sAu  = smem_u32(sA);
    const uint32_t sBu0 = smem_u32(sB[0]);
    const uint32_t sBu1 = smem_u32(sB[1]);

    // prologue: A + B0 (group), B1 (group)
    for (int i = tid; i < 512; i += 256) {
        int r = i >> 3, c = i & 7;
        cpa16(sAu + r * 128 + ((c ^ (r & 7)) << 4), (const char*)Ag + r * 128 + c * 16);
    }
    for (int i = tid; i < 1024; i += 256) {
        int r = i >> 3, c = i & 7;
        cpa16(sBu0 + r * 128 + ((c ^ (r & 7)) << 4), (const char*)Fg + r * 128 + c * 16);
    }
    CP_COMMIT();
    for (int i = tid; i < 1024; i += 256) {
        int r = i >> 3, c = i & 7;
        cpa16(sBu1 + r * 128 + ((c ^ (r & 7)) << 4),
              (const char*)Fg + (size_t)TN * 128 + r * 128 + c * 16);
    }
    CP_COMMIT();
    CP_WAIT(1);
    __syncthreads();

    // A fragments (constant across all chunks)
    uint32_t afr[4][4];
    {
        int row = wr + (l & 15);
        #pragma unroll
        for (int kk = 0; kk < 4; kk++) {
            int kb = kk * 32 + (l >> 4) * 16;
            uint32_t ad = sAu + row * 128 + (((kb >> 4) ^ (row & 7)) << 4);
            LDSM4(afr[kk][0], afr[kk][1], afr[kk][2], afr[kk][3], ad);
        }
    }

    const int r0 = wr + (l >> 2), r1 = r0 + 8;
    const bool mygrp = (g == (mytile & 1));
    const int dct = mytile >> 1;
    float rs0 = 0.f, rs1 = 0.f, d0 = 0.f, d1 = 0.f;

    const int nlane  = (l & 7) + ((l >> 4) << 3);
    const int kblane = ((l >> 3) & 1) * 16;

    for (int ct = 0; ct < NCH; ++ct) {
        const uint32_t sBu = (ct & 1) ? sBu1 : sBu0;
        const bool dg = mygrp && (ct == dct);

        #pragma unroll
        for (int jp = 0; jp < 4; ++jp) {
            float a0[4] = {0.f, 0.f, 0.f, 0.f};
            float a1[4] = {0.f, 0.f, 0.f, 0.f};
            #pragma unroll
            for (int kk = 0; kk < 4; ++kk) {
                int n  = g * 64 + jp * 16 + nlane;
                int kb = kk * 32 + kblane;
                uint32_t ad = sBu + n * 128 + (((kb >> 4) ^ (n & 7)) << 4);
                uint32_t b0, b1, b2, b3;
                LDSM4(b0, b1, b2, b3, ad);
                mma16816(a0, afr[kk], b0, b1);
                mma16816(a1, afr[kk], b2, b3);
            }
            int c00 = jp * 16 + (l & 3) * 2;
            int c10 = c00 + 8;
            if (dg) {
                if (c00     == r0) d0 = a0[0];
                if (c00 + 1 == r0) d0 = a0[1];
                if (c10     == r0) d0 = a1[0];
                if (c10 + 1 == r0) d0 = a1[1];
                if (c00     == r1) d1 = a0[2];
                if (c00 + 1 == r1) d1 = a0[3];
                if (c10     == r1) d1 = a1[2];
                if (c10 + 1 == r1) d1 = a1[3];
            }
            rs0 += ex2f(a0[0] * C2EXP) + ex2f(a0[1] * C2EXP)
                 + ex2f(a1[0] * C2EXP) + ex2f(a1[1] * C2EXP);
            rs1 += ex2f(a0[2] * C2EXP) + ex2f(a0[3] * C2EXP)
                 + ex2f(a1[2] * C2EXP) + ex2f(a1[3] * C2EXP);
        }

        __syncthreads();
        if (ct + 2 < NCH) {
            uint32_t dstB = (ct & 1) ? sBu1 : sBu0;
            const char* src = (const char*)Fg + (size_t)(ct + 2) * TN * 128;
            for (int i = tid; i < 1024; i += 256) {
                int r = i >> 3, c = i & 7;
                cpa16(dstB + r * 128 + ((c ^ (r & 7)) << 4), src + r * 128 + c * 16);
            }
            CP_COMMIT();
            CP_WAIT(1);
            __syncthreads();
        } else if (ct + 1 < NCH) {
            CP_WAIT(0);
            __syncthreads();
        }
    }

    // reduce within quads
    #pragma unroll
    for (int o = 1; o <= 2; o <<= 1) {
        rs0 += __shfl_xor_sync(0xffffffffu, rs0, o);
        rs1 += __shfl_xor_sync(0xffffffffu, rs1, o);
        d0  += __shfl_xor_sync(0xffffffffu, d0, o);
        d1  += __shfl_xor_sync(0xffffffffu, d1, o);
    }
    if ((l & 3) == 0) {
        ssum[g][r0] = rs0;
        ssum[g][r1] = rs1;
        if (mygrp) { sdiag[r0] = d0; sdiag[r1] = d1; }
    }
    __syncthreads();

    if (tid < TILE_M) {
        float tot = ssum[0][tid] + ssum[1][tid];
        sloss[tid] = logf(tot) - sdiag[tid] * INV_T;
    }
    __syncthreads();

    if (tid == 0) {
        float part = 0.f;
        #pragma unroll
        for (int i = 0; i < TILE_M; ++i) part += sloss[i];
        g_partials[cta] = part * (1.0f / (float)SS);
        __threadfence();
        int n = atomicAdd(&g_count, 1);
        if (n == NCTA - 1) {
            __threadfence();
            const volatile float* gp = (const volatile float*)g_partials;
            float tot = 0.f;
            for (int i = 0; i < NCTA; ++i) tot += gp[i];
            out[0] = tot;
            g_count = 0;   // reset for next graph replay
        }
    }
}

// ---------------------------------------------------------------- launch
extern "C" void kernel_launch(void* const* d_in, const int* in_sizes, int n_in,
                              void* d_out, int out_size) {
    const float* dv    = (const float*)d_in[0];
    const int*   vcoor = (const int*)  d_in[1];
    const float* df    = (const float*)d_in[2];
    const int*   fcoor = (const int*)  d_in[3];
    const int*   shuf  = (const int*)  d_in[4];
    // d_in[5] = vehicle_points (unused)
    const int*   samp  = (const int*)  d_in[6];

    k0<<<384, 256>>>(dv, vcoor, shuf, samp);
    k1<<<256, 256>>>(df, fcoor, samp);
    k_loss<<<NCTA, 256>>>((float*)d_out);
}

// round 10
// speedup vs baseline: 1.1412x; 1.0229x over previous
#include <cuda_runtime.h>
#include <cuda_bf16.h>
#include <cstdint>
#include <math.h>

// ---------------------------------------------------------------- constants
#define BB 4
#define NN 20000
#define SS 2048
#define CC 64
#define DD 64
#define INV_T 1.4285714285714286f
#define C2EXP 2.0609929155556624f   // INV_T * log2(e)

#define TILE_M 64
#define TN 128
#define NCH (SS / TN)          // 16 column chunks
#define TPB (SS / TILE_M)      // 32 row tiles per batch
#define NCTA (BB * TPB)        // 128 loss CTAs

// k_loss dynamic smem layout
#define OFF_A     0                  // 8 KB   (64 rows x 128 B)
#define OFF_B     8192               // 3 x 16 KB (128 rows x 128 B each)
#define OFF_SSUM  (8192 + 3*16384)   // 2*64 floats
#define OFF_SDIAG (OFF_SSUM + 512)   // 64 floats
#define OFF_SLOSS (OFF_SDIAG + 256)  // 64 floats
#define SMEM_K2   (OFF_SLOSS + 256)  // 58368 B

// ---------------------------------------------------------------- scratch
__device__ __align__(256) __nv_bfloat16 g_Vn[(size_t)BB * SS * CC];
__device__ __align__(256) __nv_bfloat16 g_Fn[(size_t)BB * SS * CC];
__device__ int   g_faddr[BB * NN];   // flat voxel index of fusion point, by original id
__device__ float g_partials[NCTA];
__device__ int   g_count;   // zero-init; reset by last CTA each run

// ---------------------------------------------------------------- helpers
__device__ __forceinline__ uint32_t smem_u32(const void* p) {
    uint32_t a;
    asm("{ .reg .u64 t; cvta.to.shared.u64 t, %1; cvt.u32.u64 %0, t; }" : "=r"(a) : "l"(p));
    return a;
}
__device__ __forceinline__ void cpa16(uint32_t dst, const void* src) {
    asm volatile("cp.async.cg.shared.global [%0], [%1], 16;" :: "r"(dst), "l"(src));
}
#define CP_COMMIT() asm volatile("cp.async.commit_group;" ::: "memory")
#define CP_WAIT(n)  asm volatile("cp.async.wait_group %0;" :: "n"(n) : "memory")

#define LDSM4(r0, r1, r2, r3, addr)                                            \
    asm volatile("ldmatrix.sync.aligned.m8n8.x4.shared.b16 {%0,%1,%2,%3}, [%4];" \
                 : "=r"(r0), "=r"(r1), "=r"(r2), "=r"(r3) : "r"(addr))

__device__ __forceinline__ void mma16816(float* c, const uint32_t* a,
                                         uint32_t b0, uint32_t b1) {
    asm volatile(
        "mma.sync.aligned.m16n8k16.row.col.f32.bf16.bf16.f32 "
        "{%0,%1,%2,%3}, {%4,%5,%6,%7}, {%8,%9}, {%0,%1,%2,%3};"
        : "+f"(c[0]), "+f"(c[1]), "+f"(c[2]), "+f"(c[3])
        : "r"(a[0]), "r"(a[1]), "r"(a[2]), "r"(a[3]), "r"(b0), "r"(b1));
}
__device__ __forceinline__ float ex2f(float x) {
    float r; asm("ex2.approx.f32 %0, %1;" : "=f"(r) : "f"(x)); return r;
}

// ---------------------------------------------------------------- kernel 0
// CTAs 0-1023: vehicle gather+normalize, 1 row/warp (max TLP).
// CTAs 1024-1151: scatter flattened fusion voxel addresses.
__global__ __launch_bounds__(256) void k0(
    const float* __restrict__ dv, const int* __restrict__ vcoor,
    const int* __restrict__ fcoor, const int* __restrict__ shuf,
    const int* __restrict__ samp_idx)
{
    const int tid = threadIdx.x;
    const int w   = tid >> 5;
    const int l   = tid & 31;
    const int cta = blockIdx.x;

    if (cta >= 1024) {
        // scatter: g_faddr[b][shuf[j]] = flat(fcoor[b][j] >> 3)
        for (int i = (cta - 1024) * 256 + tid; i < BB * NN; i += 128 * 256) {
            int b = i / NN;
            int v = shuf[i];
            const int* cp = fcoor + (size_t)i * 3;
            int c0 = cp[0] >> 3, c1 = cp[1] >> 3, c2 = cp[2] >> 3;
            g_faddr[b * NN + v] = ((b * DD + c0) * DD + c1) * DD + c2;
        }
        return;
    }

    // vehicle gather: one row per warp
    int r = cta * 8 + w;               // 0..8191
    int b = r >> 11, s = r & 2047;
    int samp = __ldg(&samp_idx[b * SS + s]);
    const int* cp = vcoor + ((size_t)b * NN + samp) * 3;
    int c0 = cp[0] >> 3, c1 = cp[1] >> 3, c2 = cp[2] >> 3;
    const float* src = dv + ((((size_t)b * DD + c0) * DD + c1) * DD + c2) * (size_t)CC;
    float v0 = src[l], v1 = src[l + 32];
    float ssq = v0 * v0 + v1 * v1;
    #pragma unroll
    for (int o = 16; o; o >>= 1) ssq += __shfl_xor_sync(0xffffffffu, ssq, o);
    float inv = 1.0f / fmaxf(sqrtf(ssq), 1e-12f);
    size_t rb = (size_t)r * CC;
    g_Vn[rb + l]      = __float2bfloat16(v0 * inv);
    g_Vn[rb + l + 32] = __float2bfloat16(v1 * inv);
}

// ---------------------------------------------------------------- kernel 1
// fusion gather via pre-flattened addresses: samp -> faddr -> feat (3-chain).
__global__ __launch_bounds__(256) void k1(
    const float* __restrict__ df, const int* __restrict__ samp_idx)
{
    const int tid = threadIdx.x;
    const int w   = tid >> 5;
    const int l   = tid & 31;

    int r = blockIdx.x * 8 + w;        // 0..8191
    int b = r >> 11, s = r & 2047;
    int samp = __ldg(&samp_idx[b * SS + s]);
    int flat = __ldg(&g_faddr[b * NN + samp]);
    const float* src = df + (size_t)flat * CC;
    float v0 = src[l], v1 = src[l + 32];
    float ssq = v0 * v0 + v1 * v1;
    #pragma unroll
    for (int o = 16; o; o >>= 1) ssq += __shfl_xor_sync(0xffffffffu, ssq, o);
    float inv = 1.0f / fmaxf(sqrtf(ssq), 1e-12f);
    size_t rb = (size_t)r * CC;
    g_Fn[rb + l]      = __float2bfloat16(v0 * inv);
    g_Fn[rb + l + 32] = __float2bfloat16(v1 * inv);
}

// ---------------------------------------------------------------- kernel 2
// Fused bf16 mma.sync GEMM (64 x 2048 x 64 per CTA) + exp/rowsum/diag + loss.
// 3-buffer cp.async pipeline: ONE __syncthreads per chunk.
__global__ __launch_bounds__(256, 1) void k_loss(float* __restrict__ out) {
    extern __shared__ __align__(128) unsigned char dsm[];
    float* ssum  = (float*)(dsm + OFF_SSUM);   // [2][64]
    float* sdiag = (float*)(dsm + OFF_SDIAG);  // [64]
    float* sloss = (float*)(dsm + OFF_SLOSS);  // [64]

    const int tid = threadIdx.x;
    const int w   = tid >> 5;
    const int l   = tid & 31;
    const int cta = blockIdx.x;
    const int b      = cta >> 5;
    const int mytile = cta & 31;
    const int g  = w >> 2;          // column half group
    const int wr = (w & 3) * 16;    // warp row base (local)

    const __nv_bfloat16* Ag = g_Vn + ((size_t)b * SS + (size_t)mytile * TILE_M) * CC;
    const __nv_bfloat16* Fg = g_Fn + (size_t)b * SS * CC;

    const uint32_t sAu = smem_u32(dsm + OFF_A);
    const uint32_t sBu[3] = { smem_u32(dsm + OFF_B),
                              smem_u32(dsm + OFF_B + 16384),
                              smem_u32(dsm + OFF_B + 32768) };

    // prologue: G0 = A + B0, G1 = B1
    for (int i = tid; i < 512; i += 256) {
        int r = i >> 3, c = i & 7;
        cpa16(sAu + r * 128 + ((c ^ (r & 7)) << 4), (const char*)Ag + r * 128 + c * 16);
    }
    for (int i = tid; i < 1024; i += 256) {
        int r = i >> 3, c = i & 7;
        cpa16(sBu[0] + r * 128 + ((c ^ (r & 7)) << 4), (const char*)Fg + r * 128 + c * 16);
    }
    CP_COMMIT();
    for (int i = tid; i < 1024; i += 256) {
        int r = i >> 3, c = i & 7;
        cpa16(sBu[1] + r * 128 + ((c ^ (r & 7)) << 4),
              (const char*)Fg + (size_t)TN * 128 + r * 128 + c * 16);
    }
    CP_COMMIT();
    CP_WAIT(1);          // A + B0 landed
    __syncthreads();

    // A fragments (constant across all chunks)
    uint32_t afr[4][4];
    {
        int row = wr + (l & 15);
        #pragma unroll
        for (int kk = 0; kk < 4; kk++) {
            int kb = kk * 32 + (l >> 4) * 16;
            uint32_t ad = sAu + row * 128 + (((kb >> 4) ^ (row & 7)) << 4);
            LDSM4(afr[kk][0], afr[kk][1], afr[kk][2], afr[kk][3], ad);
        }
    }

    const int r0 = wr + (l >> 2), r1 = r0 + 8;
    const bool mygrp = (g == (mytile & 1));
    const int dct = mytile >> 1;
    float rs0 = 0.f, rs1 = 0.f, d0 = 0.f, d1 = 0.f;

    const int nlane  = (l & 7) + ((l >> 4) << 3);
    const int kblane = ((l >> 3) & 1) * 16;

    for (int ct = 0; ct < NCH; ++ct) {
        CP_WAIT(1);          // group(ct) complete (<=1 outstanding: ct+1)
        __syncthreads();     // visibility + all warps done with buf[(ct+2)%3]

        // prefetch chunk ct+2 into buf[(ct+2)%3] (consumed at iter ct-1)
        if (ct + 2 < NCH) {
            uint32_t dstB = sBu[(ct + 2) % 3];
            const char* src = (const char*)Fg + (size_t)(ct + 2) * TN * 128;
            for (int i = tid; i < 1024; i += 256) {
                int r = i >> 3, c = i & 7;
                cpa16(dstB + r * 128 + ((c ^ (r & 7)) << 4), src + r * 128 + c * 16);
            }
            CP_COMMIT();
        }

        const uint32_t sBc = sBu[ct % 3];
        const bool dg = mygrp && (ct == dct);

        #pragma unroll
        for (int jp = 0; jp < 4; ++jp) {
            float a0[4] = {0.f, 0.f, 0.f, 0.f};
            float a1[4] = {0.f, 0.f, 0.f, 0.f};
            #pragma unroll
            for (int kk = 0; kk < 4; ++kk) {
                int n  = g * 64 + jp * 16 + nlane;
                int kb = kk * 32 + kblane;
                uint32_t ad = sBc + n * 128 + (((kb >> 4) ^ (n & 7)) << 4);
                uint32_t b0, b1, b2, b3;
                LDSM4(b0, b1, b2, b3, ad);
                mma16816(a0, afr[kk], b0, b1);
                mma16816(a1, afr[kk], b2, b3);
            }
            int c00 = jp * 16 + (l & 3) * 2;
            int c10 = c00 + 8;
            if (dg) {
                if (c00     == r0) d0 = a0[0];
                if (c00 + 1 == r0) d0 = a0[1];
                if (c10     == r0) d0 = a1[0];
                if (c10 + 1 == r0) d0 = a1[1];
                if (c00     == r1) d1 = a0[2];
                if (c00 + 1 == r1) d1 = a0[3];
                if (c10     == r1) d1 = a1[2];
                if (c10 + 1 == r1) d1 = a1[3];
            }
            rs0 += ex2f(a0[0] * C2EXP) + ex2f(a0[1] * C2EXP)
                 + ex2f(a1[0] * C2EXP) + ex2f(a1[1] * C2EXP);
            rs1 += ex2f(a0[2] * C2EXP) + ex2f(a0[3] * C2EXP)
                 + ex2f(a1[2] * C2EXP) + ex2f(a1[3] * C2EXP);
        }
    }

    // reduce within quads
    #pragma unroll
    for (int o = 1; o <= 2; o <<= 1) {
        rs0 += __shfl_xor_sync(0xffffffffu, rs0, o);
        rs1 += __shfl_xor_sync(0xffffffffu, rs1, o);
        d0  += __shfl_xor_sync(0xffffffffu, d0, o);
        d1  += __shfl_xor_sync(0xffffffffu, d1, o);
    }
    if ((l & 3) == 0) {
        ssum[g * TILE_M + r0] = rs0;
        ssum[g * TILE_M + r1] = rs1;
        if (mygrp) { sdiag[r0] = d0; sdiag[r1] = d1; }
    }
    __syncthreads();

    if (tid < TILE_M) {
        float tot = ssum[tid] + ssum[TILE_M + tid];
        sloss[tid] = logf(tot) - sdiag[tid] * INV_T;
    }
    __syncthreads();

    if (tid == 0) {
        float part = 0.f;
        #pragma unroll
        for (int i = 0; i < TILE_M; ++i) part += sloss[i];
        g_partials[cta] = part * (1.0f / (float)SS);
        __threadfence();
        int n = atomicAdd(&g_count, 1);
        if (n == NCTA - 1) {
            __threadfence();
            const volatile float* gp = (const volatile float*)g_partials;
            float tot = 0.f;
            for (int i = 0; i < NCTA; ++i) tot += gp[i];
            out[0] = tot;
            g_count = 0;   // reset for next graph replay
        }
    }
}

// ---------------------------------------------------------------- launch
extern "C" void kernel_launch(void* const* d_in, const int* in_sizes, int n_in,
                              void* d_out, int out_size) {
    const float* dv    = (const float*)d_in[0];
    const int*   vcoor = (const int*)  d_in[1];
    const float* df    = (const float*)d_in[2];
    const int*   fcoor = (const int*)  d_in[3];
    const int*   shuf  = (const int*)  d_in[4];
    // d_in[5] = vehicle_points (unused)
    const int*   samp  = (const int*)  d_in[6];

    cudaFuncSetAttribute(k_loss, cudaFuncAttributeMaxDynamicSharedMemorySize, SMEM_K2);

    k0<<<1152, 256>>>(dv, vcoor, fcoor, shuf, samp);
    k1<<<1024, 256>>>(df, samp);
    k_loss<<<NCTA, 256, SMEM_K2>>>((float*)d_out);
}